// round 16
// baseline (speedup 1.0000x reference)
#include <cuda_runtime.h>
#include <cstdint>

// ============================================================
// mma.sync (HMMA) bf16 3-pass split — sm_103-base safe.
// Per 32-node tile: D[128,64] = Ah*Bh + Al*Bh + Ah*Bl, fp32 accum in regs.
//   A rows: nloc*4 + comp (comp0 = x0, comp1..3 = x1[:,i]); K = 128 (u)
//   B rows j (= output col): 0:16 w000 | 16:32 w011 | 32:48 w110 | 48:64 w101
//   (0.01*C folded into B). B fragment-pair interleaved, 72-word rows ->
//   conflict-free LDS.64. Inner loop: batched B loads, nt-swept MMAs for
//   dependency distance.
// ============================================================

#define TPC 10
#define NT  256

// smem layout (bytes from dynamic base)
#define SM_BH   0                 // Bh: 64 rows x 288B = 18432
#define SM_BL   18432             // Bl: 18432
#define SM_A    36864             // Ah: 128 rows x 272B = 34816 (D dump aliases)
#define SM_AL   71680             // Al: 34816
#define SMEM_TOTAL 106496         // x2 CTAs = 212992 <= 227KB
#define DW  9216                  // = SM_A/4; D stride 68 words
#define AST 272                   // A row stride (bytes)
#define BST 72                    // B row stride (words)

__device__ __forceinline__ uint32_t smem_u32(const void* p) {
    uint32_t a;
    asm("{ .reg .u64 t; cvta.to.shared.u64 t, %1; cvt.u32.u64 %0, t; }"
        : "=r"(a) : "l"(p));
    return a;
}
__device__ __forceinline__ uint32_t packbf(float lo, float hi) {
    uint32_t r;   // hi -> upper 16 bits, lo -> lower 16 bits
    asm("cvt.rn.satfinite.bf16x2.f32 %0, %1, %2;" : "=r"(r) : "f"(hi), "f"(lo));
    return r;
}
__device__ __forceinline__ float bflo(uint32_t p) { return __uint_as_float(p << 16); }
__device__ __forceinline__ float bfhi(uint32_t p) { return __uint_as_float(p & 0xFFFF0000u); }
__device__ __forceinline__ void sts32(uint32_t a, uint32_t v) {
    asm volatile("st.shared.b32 [%0], %1;" :: "r"(a), "r"(v) : "memory");
}
__device__ __forceinline__ void sts64(uint32_t a, uint32_t v0, uint32_t v1) {
    asm volatile("st.shared.v2.b32 [%0], {%1,%2};" :: "r"(a), "r"(v0), "r"(v1) : "memory");
}
__device__ __forceinline__ void lds64(uint32_t &v0, uint32_t &v1, uint32_t a) {
    asm volatile("ld.shared.v2.b32 {%0,%1}, [%2];" : "=r"(v0), "=r"(v1) : "r"(a));
}
#define LDSM4(r, addr) \
    asm volatile("ldmatrix.sync.aligned.m8n8.x4.shared.b16 {%0,%1,%2,%3}, [%4];" \
        : "=r"((r)[0]), "=r"((r)[1]), "=r"((r)[2]), "=r"((r)[3]) : "r"(addr))
#define MMA16816(c, a, b0, b1) \
    asm volatile("mma.sync.aligned.m16n8k16.row.col.f32.bf16.bf16.f32 " \
        "{%0,%1,%2,%3}, {%4,%5,%6,%7}, {%8,%9}, {%0,%1,%2,%3};" \
        : "+f"((c)[0]), "+f"((c)[1]), "+f"((c)[2]), "+f"((c)[3]) \
        : "r"((a)[0]), "r"((a)[1]), "r"((a)[2]), "r"((a)[3]), "r"(b0), "r"(b1))

__global__ void __launch_bounds__(NT, 2) fctp_mma(
    const float* __restrict__ nf, const float* __restrict__ pf,
    const float* __restrict__ w000, const float* __restrict__ w011,
    const float* __restrict__ w101, const float* __restrict__ w110,
    float* __restrict__ out, int nTiles)
{
    extern __shared__ float S[];
    const uint32_t sb = smem_u32(S);
    const int tid = threadIdx.x;
    const int warp = tid >> 5, lane = tid & 31;
    const int g = lane >> 2, t = lane & 3;

    const int tile0 = blockIdx.x * TPC;
    const int myTiles = min(TPC, nTiles - tile0);
    if (myTiles <= 0) return;

    // ---- build Bh/Bl: fragment-pair interleaved, 72-word rows ----
    {
        const float c000 = 3.125e-4f;                // 0.01/32
        const float c110 = 1.8042195912175807e-4f;   // 0.01/(32*sqrt(3))
        int j = tid >> 2, q = tid & 3;
        const float* wsrc = (j < 16) ? w000 : (j < 32) ? w011 : (j < 48) ? w110 : w101;
        float cs = (j >= 32 && j < 48) ? c110 : c000;
        int jj = j & 15;
        #pragma unroll
        for (int gg = 0; gg < 16; gg++) {
            int w = q * 16 + gg;                      // K-word index (k = 2w)
            int k = 2 * w;
            float f0 = cs * wsrc[k * 16 + jj];
            float f1 = cs * wsrc[(k + 1) * 16 + jj];
            uint32_t hp = packbf(f0, f1);
            uint32_t lp = packbf(f0 - bflo(hp), f1 - bfhi(hp));
            int kk = w >> 3, m = w & 7;
            int pos = 8 * kk + ((m < 4) ? 2 * m : 2 * m - 7);
            uint32_t wo = (uint32_t)(j * BST + pos) * 4u;
            sts32(sb + SM_BH + wo, hp);
            sts32(sb + SM_BL + wo, lp);
        }
    }
    __syncthreads();   // B visible

    // ldmatrix per-lane base within A tiles (warp strip = rows 16w..16w+15)
    const uint32_t lm_off =
        (uint32_t)((16 * warp + (lane & 15)) * AST + (lane >> 4) * 16);
    // per-lane B fragment base offset (words): row g, +2t within fragment pairs
    const uint32_t bfrag = (uint32_t)(g * BST + 2 * t) * 4u;

    for (int j = 0; j < myTiles; j++) {
        const int tnode0 = (tile0 + j) * 32;
        const float* xb = nf + (size_t)tnode0 * 512;

        // ---- convert global fp32 -> Ah/Al (bf16, 272B row stride) ----
        #pragma unroll
        for (int i = 0; i < 4; i++) {              // x0: 1024 float4 total
            int e = i * NT + tid;
            int nd = e >> 5, q = e & 31;           // warp covers one node row
            float4 f = *reinterpret_cast<const float4*>(xb + (size_t)nd * 512 + 4 * q);
            uint32_t h0 = packbf(f.x, f.y), h1 = packbf(f.z, f.w);
            uint32_t l0 = packbf(f.x - bflo(h0), f.y - bfhi(h0));
            uint32_t l1 = packbf(f.z - bflo(h1), f.w - bfhi(h1));
            uint32_t ro = (uint32_t)((nd * 4) * AST + 8 * q);
            sts64(sb + SM_A  + ro, h0, h1);
            sts64(sb + SM_AL + ro, l0, l1);
        }
        #pragma unroll
        for (int i = 0; i < 4; i++) {              // x1: groups of 12 floats (u=4q..4q+3)
            int e = i * NT + tid;
            int nd = e >> 5, q = e & 31;
            const float* rp = xb + (size_t)nd * 512 + 128 + 12 * q;
            float4 fa = *reinterpret_cast<const float4*>(rp);
            float4 fb = *reinterpret_cast<const float4*>(rp + 4);
            float4 fc = *reinterpret_cast<const float4*>(rp + 8);
            float f[12] = { fa.x, fa.y, fa.z, fa.w,
                            fb.x, fb.y, fb.z, fb.w,
                            fc.x, fc.y, fc.z, fc.w };
            #pragma unroll
            for (int c = 0; c < 3; c++) {
                float f0 = f[c], f1 = f[3 + c], f2 = f[6 + c], f3 = f[9 + c];
                uint32_t h0 = packbf(f0, f1), h1 = packbf(f2, f3);
                uint32_t l0 = packbf(f0 - bflo(h0), f1 - bfhi(h0));
                uint32_t l1 = packbf(f2 - bflo(h1), f3 - bfhi(h1));
                uint32_t ro = (uint32_t)((nd * 4 + 1 + c) * AST + 8 * q);
                sts64(sb + SM_A  + ro, h0, h1);
                sts64(sb + SM_AL + ro, l0, l1);
            }
        }
        __syncthreads();   // A tiles ready

        float acc[8][4];
        #pragma unroll
        for (int nt = 0; nt < 8; nt++)
            #pragma unroll
            for (int c = 0; c < 4; c++) acc[nt][c] = 0.0f;

        // ---- fused 3-pass MMA: per kk, batch B loads then sweep nt ----
        #pragma unroll
        for (int kk = 0; kk < 8; kk++) {
            uint32_t ah[4], al[4];
            LDSM4(ah, sb + SM_A  + lm_off + 32 * kk);
            LDSM4(al, sb + SM_AL + lm_off + 32 * kk);

            uint32_t bh[16], bl[16];
            #pragma unroll
            for (int nt = 0; nt < 8; nt++)
                lds64(bh[2*nt], bh[2*nt+1],
                      sb + SM_BH + bfrag + (uint32_t)(8 * nt * BST + 8 * kk) * 4u);
            #pragma unroll
            for (int nt = 0; nt < 8; nt++)
                lds64(bl[2*nt], bl[2*nt+1],
                      sb + SM_BL + bfrag + (uint32_t)(8 * nt * BST + 8 * kk) * 4u);

            #pragma unroll
            for (int nt = 0; nt < 8; nt++)
                MMA16816(acc[nt], ah, bh[2*nt], bh[2*nt+1]);
            #pragma unroll
            for (int nt = 0; nt < 8; nt++)
                MMA16816(acc[nt], al, bh[2*nt], bh[2*nt+1]);
            #pragma unroll
            for (int nt = 0; nt < 8; nt++)
                MMA16816(acc[nt], ah, bl[2*nt], bl[2*nt+1]);
        }
        __syncthreads();   // all warps done reading A region

        // ---- dump D (aliases Ah region; 68-word row stride) ----
        {
            int r0 = 16 * warp + g, r1 = r0 + 8;
            #pragma unroll
            for (int nt = 0; nt < 8; nt++) {
                uint32_t col = (uint32_t)(8 * nt + 2 * t);
                sts64(sb + SM_A + (uint32_t)(r0 * 68 + col) * 4u,
                      __float_as_uint(acc[nt][0]), __float_as_uint(acc[nt][1]));
                sts64(sb + SM_A + (uint32_t)(r1 * 68 + col) * 4u,
                      __float_as_uint(acc[nt][2]), __float_as_uint(acc[nt][3]));
            }
        }
        __syncthreads();   // D visible

        // ---- epilogue: 8 threads per node, 2 outputs each ----
        {
            int nd = tid >> 3, s = tid & 7;
            int node = tnode0 + nd;
            const float* yp = pf + (size_t)node * 16;
            float y0v[4], y1f[12];
            #pragma unroll
            for (int v = 0; v < 4; v++) y0v[v] = yp[v];
            #pragma unroll
            for (int e = 0; e < 12; e++) y1f[e] = yp[4 + e];

            const float* Dp = S + DW + nd * 4 * 68;   // comp0 row of this node
            float res[2];
            #pragma unroll
            for (int e2 = 0; e2 < 2; e2++) {
                int oi = 2 * s + e2;
                float a = 0.0f;
                if (oi < 4) {                          // out0[w=oi]
                    #pragma unroll
                    for (int v = 0; v < 4; v++)
                        a += Dp[v * 4 + oi] * y0v[v];
                    #pragma unroll
                    for (int ii = 0; ii < 3; ii++)
                        #pragma unroll
                        for (int v = 0; v < 4; v++)
                            a += Dp[(1 + ii) * 68 + 32 + v * 4 + oi] * y1f[v * 3 + ii];
                } else {                               // out1[wq][kq]
                    int r = oi - 4;
                    int wq = r / 3, kq = r - wq * 3;
                    #pragma unroll
                    for (int v = 0; v < 4; v++)
                        a += Dp[16 + v * 4 + wq] * y1f[v * 3 + kq];
                    #pragma unroll
                    for (int v = 0; v < 4; v++)
                        a += Dp[(1 + kq) * 68 + 48 + v * 4 + wq] * y0v[v];
                }
                res[e2] = a;
            }
            if (s == 0) res[0] = 0.0f;   // reference zeroes out[:,0]
            *reinterpret_cast<float2*>(out + (size_t)node * 16 + 2 * s) =
                make_float2(res[0], res[1]);
        }
        __syncthreads();   // epilogue done with D before next conversion
    }
}

// naive tail kernel for n % 32 != 0 (not hit for n=400000)
__global__ void fctp_tail(
    const float* __restrict__ nf, const float* __restrict__ pf,
    const float* __restrict__ w000, const float* __restrict__ w011,
    const float* __restrict__ w101, const float* __restrict__ w110,
    float* __restrict__ out, int start, int n)
{
    int node = start + blockIdx.x * blockDim.x + threadIdx.x;
    if (node >= n) return;
    const float* x = nf + (size_t)node * 512;
    const float* y = pf + (size_t)node * 16;
    float y0v[4], y1v[4][3];
    for (int v0 = 0; v0 < 4; v0++) {
        y0v[v0] = y[v0];
        for (int i = 0; i < 3; i++) y1v[v0][i] = y[4 + 3 * v0 + i];
    }
    float o0[4] = {0, 0, 0, 0}, o1[4][3] = {};
    for (int u = 0; u < 128; u++) {
        float x0u = x[u];
        float x1u[3] = { x[128 + 3*u], x[128 + 3*u + 1], x[128 + 3*u + 2] };
        for (int v0 = 0; v0 < 4; v0++) {
            float s110 = x1u[0]*y1v[v0][0] + x1u[1]*y1v[v0][1] + x1u[2]*y1v[v0][2];
            float xy0 = x0u * y0v[v0];
            for (int w = 0; w < 4; w++) {
                int idx = u*16 + v0*4 + w;
                o0[w] += 3.125e-4f * xy0 * w000[idx]
                       + 1.8042195912175807e-4f * s110 * w110[idx];
                for (int k = 0; k < 3; k++)
                    o1[w][k] += 3.125e-4f * (x0u * y1v[v0][k] * w011[idx]
                                           + x1u[k] * y0v[v0] * w101[idx]);
            }
        }
    }
    o0[0] = 0.0f;
    float* op = out + (size_t)node * 16;
    for (int w = 0; w < 4; w++) op[w] = o0[w];
    for (int w = 0; w < 4; w++)
        for (int k = 0; k < 3; k++) op[4 + 3*w + k] = o1[w][k];
}

extern "C" void kernel_launch(void* const* d_in, const int* in_sizes, int n_in,
                              void* d_out, int out_size) {
    const float* nf   = (const float*)d_in[0];
    const float* pf   = (const float*)d_in[1];
    const float* w000 = (const float*)d_in[2];
    const float* w011 = (const float*)d_in[3];
    const float* w101 = (const float*)d_in[4];
    const float* w110 = (const float*)d_in[5];
    float* out = (float*)d_out;
    int n = in_sizes[0] / 512;
    int nTiles = n / 32;
    int rem = n - nTiles * 32;
    cudaFuncSetAttribute(fctp_mma, cudaFuncAttributeMaxDynamicSharedMemorySize, SMEM_TOTAL);
    if (nTiles > 0) {
        int grid = (nTiles + TPC - 1) / TPC;
        fctp_mma<<<grid, NT, SMEM_TOTAL>>>(nf, pf, w000, w011, w101, w110, out, nTiles);
    }
    if (rem > 0)
        fctp_tail<<<1, 128>>>(nf, pf, w000, w011, w101, w110, out, nTiles * 32, n);
}

// round 17
// speedup vs baseline: 1.1647x; 1.1647x over previous
#include <cuda_runtime.h>
#include <cstdint>

// ============================================================
// mma.sync (HMMA) bf16 3-pass split, TWO exact GEMMs — sm_103-base safe.
//   A tile (shared storage): row nloc*4 + comp (comp0 = x0, comp1..3 = x1[:,i])
//   G1 (warps 0-1): A rows {4nd}       x B rows  0..31 ([w000|w011])
//   G2 (warps 2-7): A rows {4nd+1+ic}  x B rows 32..63 ([w110|w101])
//   D = Ah*Bh + Al*Bh + Ah*Bl, fp32 accum in regs. 0.01*C folded into B.
//   B fragment-pair interleaved, 72-word rows -> conflict-free LDS.64.
// ============================================================

#define TPC 10
#define NT  256

// smem layout (bytes from dynamic base)
#define SM_BH   0                 // Bh: 64 rows x 288B = 18432
#define SM_BL   18432             // Bl: 18432
#define SM_A    36864             // Ah: 128 rows x 272B = 34816 (D dump aliases)
#define SM_AL   71680             // Al: 34816
#define SMEM_TOTAL 106496         // x2 CTAs = 212992 <= 227KB
#define DW  9216                  // = SM_A/4; D: 128 rows x 36-word stride
#define AST 272                   // A row stride (bytes)
#define BST 72                    // B row stride (words)
#define DST 36                    // D row stride (words)

__device__ __forceinline__ uint32_t smem_u32(const void* p) {
    uint32_t a;
    asm("{ .reg .u64 t; cvta.to.shared.u64 t, %1; cvt.u32.u64 %0, t; }"
        : "=r"(a) : "l"(p));
    return a;
}
__device__ __forceinline__ uint32_t packbf(float lo, float hi) {
    uint32_t r;   // hi -> upper 16 bits, lo -> lower 16 bits
    asm("cvt.rn.satfinite.bf16x2.f32 %0, %1, %2;" : "=r"(r) : "f"(hi), "f"(lo));
    return r;
}
__device__ __forceinline__ float bflo(uint32_t p) { return __uint_as_float(p << 16); }
__device__ __forceinline__ float bfhi(uint32_t p) { return __uint_as_float(p & 0xFFFF0000u); }
__device__ __forceinline__ void sts32(uint32_t a, uint32_t v) {
    asm volatile("st.shared.b32 [%0], %1;" :: "r"(a), "r"(v) : "memory");
}
__device__ __forceinline__ void sts64(uint32_t a, uint32_t v0, uint32_t v1) {
    asm volatile("st.shared.v2.b32 [%0], {%1,%2};" :: "r"(a), "r"(v0), "r"(v1) : "memory");
}
__device__ __forceinline__ void lds64(uint32_t &v0, uint32_t &v1, uint32_t a) {
    asm volatile("ld.shared.v2.b32 {%0,%1}, [%2];" : "=r"(v0), "=r"(v1) : "r"(a));
}
#define LDSM4(r, addr) \
    asm volatile("ldmatrix.sync.aligned.m8n8.x4.shared.b16 {%0,%1,%2,%3}, [%4];" \
        : "=r"((r)[0]), "=r"((r)[1]), "=r"((r)[2]), "=r"((r)[3]) : "r"(addr))
#define MMA16816(c, a, b0, b1) \
    asm volatile("mma.sync.aligned.m16n8k16.row.col.f32.bf16.bf16.f32 " \
        "{%0,%1,%2,%3}, {%4,%5,%6,%7}, {%8,%9}, {%0,%1,%2,%3};" \
        : "+f"((c)[0]), "+f"((c)[1]), "+f"((c)[2]), "+f"((c)[3]) \
        : "r"((a)[0]), "r"((a)[1]), "r"((a)[2]), "r"((a)[3]), "r"(b0), "r"(b1))

__global__ void __launch_bounds__(NT, 2) fctp_mma(
    const float* __restrict__ nf, const float* __restrict__ pf,
    const float* __restrict__ w000, const float* __restrict__ w011,
    const float* __restrict__ w101, const float* __restrict__ w110,
    float* __restrict__ out, int nTiles)
{
    extern __shared__ float S[];
    const uint32_t sb = smem_u32(S);
    const int tid = threadIdx.x;
    const int warp = tid >> 5, lane = tid & 31;
    const int g = lane >> 2, t = lane & 3;

    const int tile0 = blockIdx.x * TPC;
    const int myTiles = min(TPC, nTiles - tile0);
    if (myTiles <= 0) return;

    // ---- build Bh/Bl: fragment-pair interleaved, 72-word rows ----
    {
        const float c000 = 3.125e-4f;                // 0.01/32
        const float c110 = 1.8042195912175807e-4f;   // 0.01/(32*sqrt(3))
        int j = tid >> 2, q = tid & 3;
        const float* wsrc = (j < 16) ? w000 : (j < 32) ? w011 : (j < 48) ? w110 : w101;
        float cs = (j >= 32 && j < 48) ? c110 : c000;
        int jj = j & 15;
        #pragma unroll
        for (int gg = 0; gg < 16; gg++) {
            int w = q * 16 + gg;                      // K-word index (k = 2w)
            int k = 2 * w;
            float f0 = cs * wsrc[k * 16 + jj];
            float f1 = cs * wsrc[(k + 1) * 16 + jj];
            uint32_t hp = packbf(f0, f1);
            uint32_t lp = packbf(f0 - bflo(hp), f1 - bfhi(hp));
            int kk = w >> 3, m = w & 7;
            int pos = 8 * kk + ((m < 4) ? 2 * m : 2 * m - 7);
            uint32_t wo = (uint32_t)(j * BST + pos) * 4u;
            sts32(sb + SM_BH + wo, hp);
            sts32(sb + SM_BL + wo, lp);
        }
    }
    __syncthreads();   // B visible

    // ---- per-warp GEMM assignment ----
    // G1 (warps 0-1): A rows 4*(16*warp + lidx), B rows 0..31
    // G2 (warps 2-7): linear = 16*(warp-2)+lidx -> A row 4*(lin/3)+1+lin%3,
    //                 B rows 32..63
    const int lidx = lane & 15;
    int arow;
    if (warp < 2) {
        arow = 4 * (16 * warp + lidx);
    } else {
        int lin = 16 * (warp - 2) + lidx;
        arow = 4 * (lin / 3) + 1 + lin % 3;
    }
    const uint32_t lm_off = (uint32_t)(arow * AST + (lane >> 4) * 16);
    const int browB = (warp < 2) ? 0 : 32;
    // B fragment base (words): row browB + g, +2t within pair slots
    const uint32_t bfrag = (uint32_t)((browB + g) * BST + 2 * t) * 4u;

    // D dump rows (D row index = A row index; strip rows g and g+8)
    int r_lo, r_hi;
    if (warp < 2) {
        r_lo = 4 * (16 * warp + g);
        r_hi = 4 * (16 * warp + g + 8);
    } else {
        int l0 = 16 * (warp - 2) + g, l1 = l0 + 8;
        r_lo = 4 * (l0 / 3) + 1 + l0 % 3;
        r_hi = 4 * (l1 / 3) + 1 + l1 % 3;
    }

    for (int j = 0; j < myTiles; j++) {
        const int tnode0 = (tile0 + j) * 32;
        const float* xb = nf + (size_t)tnode0 * 512;

        // ---- convert global fp32 -> Ah/Al (bf16, 272B row stride) ----
        #pragma unroll
        for (int i = 0; i < 4; i++) {              // x0: 1024 float4 total
            int e = i * NT + tid;
            int nd = e >> 5, q = e & 31;           // warp covers one node row
            float4 f = *reinterpret_cast<const float4*>(xb + (size_t)nd * 512 + 4 * q);
            uint32_t h0 = packbf(f.x, f.y), h1 = packbf(f.z, f.w);
            uint32_t l0 = packbf(f.x - bflo(h0), f.y - bfhi(h0));
            uint32_t l1 = packbf(f.z - bflo(h1), f.w - bfhi(h1));
            uint32_t ro = (uint32_t)((nd * 4) * AST + 8 * q);
            sts64(sb + SM_A  + ro, h0, h1);
            sts64(sb + SM_AL + ro, l0, l1);
        }
        #pragma unroll
        for (int i = 0; i < 4; i++) {              // x1: groups of 12 floats (u=4q..4q+3)
            int e = i * NT + tid;
            int nd = e >> 5, q = e & 31;
            const float* rp = xb + (size_t)nd * 512 + 128 + 12 * q;
            float4 fa = *reinterpret_cast<const float4*>(rp);
            float4 fb = *reinterpret_cast<const float4*>(rp + 4);
            float4 fc = *reinterpret_cast<const float4*>(rp + 8);
            float f[12] = { fa.x, fa.y, fa.z, fa.w,
                            fb.x, fb.y, fb.z, fb.w,
                            fc.x, fc.y, fc.z, fc.w };
            #pragma unroll
            for (int c = 0; c < 3; c++) {
                float f0 = f[c], f1 = f[3 + c], f2 = f[6 + c], f3 = f[9 + c];
                uint32_t h0 = packbf(f0, f1), h1 = packbf(f2, f3);
                uint32_t l0 = packbf(f0 - bflo(h0), f1 - bfhi(h0));
                uint32_t l1 = packbf(f2 - bflo(h1), f3 - bfhi(h1));
                uint32_t ro = (uint32_t)((nd * 4 + 1 + c) * AST + 8 * q);
                sts64(sb + SM_A  + ro, h0, h1);
                sts64(sb + SM_AL + ro, l0, l1);
            }
        }
        __syncthreads();   // A tiles ready

        float acc[4][4];
        #pragma unroll
        for (int nt = 0; nt < 4; nt++)
            #pragma unroll
            for (int c = 0; c < 4; c++) acc[nt][c] = 0.0f;

        // ---- fused 3-pass MMA over this warp's 16x32 strip ----
        #pragma unroll
        for (int kk = 0; kk < 8; kk++) {
            uint32_t ah[4], al[4];
            LDSM4(ah, sb + SM_A  + lm_off + 32 * kk);
            LDSM4(al, sb + SM_AL + lm_off + 32 * kk);

            uint32_t bh[8], bl[8];
            #pragma unroll
            for (int nt = 0; nt < 4; nt++)
                lds64(bh[2*nt], bh[2*nt+1],
                      sb + SM_BH + bfrag + (uint32_t)(8 * nt * BST + 8 * kk) * 4u);
            #pragma unroll
            for (int nt = 0; nt < 4; nt++)
                lds64(bl[2*nt], bl[2*nt+1],
                      sb + SM_BL + bfrag + (uint32_t)(8 * nt * BST + 8 * kk) * 4u);

            #pragma unroll
            for (int nt = 0; nt < 4; nt++)
                MMA16816(acc[nt], ah, bh[2*nt], bh[2*nt+1]);
            #pragma unroll
            for (int nt = 0; nt < 4; nt++)
                MMA16816(acc[nt], al, bh[2*nt], bh[2*nt+1]);
            #pragma unroll
            for (int nt = 0; nt < 4; nt++)
                MMA16816(acc[nt], ah, bl[2*nt], bl[2*nt+1]);
        }
        __syncthreads();   // all warps done reading A region

        // ---- dump D (aliases A region; row = A row, 36-word stride) ----
        {
            #pragma unroll
            for (int nt = 0; nt < 4; nt++) {
                uint32_t col = (uint32_t)(8 * nt + 2 * t);
                sts64(sb + SM_A + (uint32_t)(r_lo * DST + col) * 4u,
                      __float_as_uint(acc[nt][0]), __float_as_uint(acc[nt][1]));
                sts64(sb + SM_A + (uint32_t)(r_hi * DST + col) * 4u,
                      __float_as_uint(acc[nt][2]), __float_as_uint(acc[nt][3]));
            }
        }
        __syncthreads();   // D visible

        // ---- epilogue: 8 threads per node, 2 outputs each ----
        // D[4nd][c]: c<16 -> Z000[c], c>=16 -> Z011[c-16]
        // D[4nd+1+i][c]: c<16 -> Z110[i][c], c>=16 -> Z101[i][c-16]
        {
            int nd = tid >> 3, s = tid & 7;
            int node = tnode0 + nd;
            const float* yp = pf + (size_t)node * 16;
            float y0v[4], y1f[12];
            #pragma unroll
            for (int v = 0; v < 4; v++) y0v[v] = yp[v];
            #pragma unroll
            for (int e = 0; e < 12; e++) y1f[e] = yp[4 + e];

            const float* Dp = S + DW + nd * 4 * DST;   // row 4nd
            float res[2];
            #pragma unroll
            for (int e2 = 0; e2 < 2; e2++) {
                int oi = 2 * s + e2;
                float a = 0.0f;
                if (oi < 4) {                          // out0[w=oi]
                    #pragma unroll
                    for (int v = 0; v < 4; v++)
                        a += Dp[v * 4 + oi] * y0v[v];
                    #pragma unroll
                    for (int ii = 0; ii < 3; ii++)
                        #pragma unroll
                        for (int v = 0; v < 4; v++)
                            a += Dp[(1 + ii) * DST + v * 4 + oi] * y1f[v * 3 + ii];
                } else {                               // out1[wq][kq]
                    int r = oi - 4;
                    int wq = r / 3, kq = r - wq * 3;
                    #pragma unroll
                    for (int v = 0; v < 4; v++)
                        a += Dp[16 + v * 4 + wq] * y1f[v * 3 + kq];
                    #pragma unroll
                    for (int v = 0; v < 4; v++)
                        a += Dp[(1 + kq) * DST + 16 + v * 4 + wq] * y0v[v];
                }
                res[e2] = a;
            }
            if (s == 0) res[0] = 0.0f;   // reference zeroes out[:,0]
            *reinterpret_cast<float2*>(out + (size_t)node * 16 + 2 * s) =
                make_float2(res[0], res[1]);
        }
        __syncthreads();   // epilogue done with D before next conversion
    }
}

// naive tail kernel for n % 32 != 0 (not hit for n=400000)
__global__ void fctp_tail(
    const float* __restrict__ nf, const float* __restrict__ pf,
    const float* __restrict__ w000, const float* __restrict__ w011,
    const float* __restrict__ w101, const float* __restrict__ w110,
    float* __restrict__ out, int start, int n)
{
    int node = start + blockIdx.x * blockDim.x + threadIdx.x;
    if (node >= n) return;
    const float* x = nf + (size_t)node * 512;
    const float* y = pf + (size_t)node * 16;
    float y0v[4], y1v[4][3];
    for (int v0 = 0; v0 < 4; v0++) {
        y0v[v0] = y[v0];
        for (int i = 0; i < 3; i++) y1v[v0][i] = y[4 + 3 * v0 + i];
    }
    float o0[4] = {0, 0, 0, 0}, o1[4][3] = {};
    for (int u = 0; u < 128; u++) {
        float x0u = x[u];
        float x1u[3] = { x[128 + 3*u], x[128 + 3*u + 1], x[128 + 3*u + 2] };
        for (int v0 = 0; v0 < 4; v0++) {
            float s110 = x1u[0]*y1v[v0][0] + x1u[1]*y1v[v0][1] + x1u[2]*y1v[v0][2];
            float xy0 = x0u * y0v[v0];
            for (int w = 0; w < 4; w++) {
                int idx = u*16 + v0*4 + w;
                o0[w] += 3.125e-4f * xy0 * w000[idx]
                       + 1.8042195912175807e-4f * s110 * w110[idx];
                for (int k = 0; k < 3; k++)
                    o1[w][k] += 3.125e-4f * (x0u * y1v[v0][k] * w011[idx]
                                           + x1u[k] * y0v[v0] * w101[idx]);
            }
        }
    }
    o0[0] = 0.0f;
    float* op = out + (size_t)node * 16;
    for (int w = 0; w < 4; w++) op[w] = o0[w];
    for (int w = 0; w < 4; w++)
        for (int k = 0; k < 3; k++) op[4 + 3*w + k] = o1[w][k];
}

extern "C" void kernel_launch(void* const* d_in, const int* in_sizes, int n_in,
                              void* d_out, int out_size) {
    const float* nf   = (const float*)d_in[0];
    const float* pf   = (const float*)d_in[1];
    const float* w000 = (const float*)d_in[2];
    const float* w011 = (const float*)d_in[3];
    const float* w101 = (const float*)d_in[4];
    const float* w110 = (const float*)d_in[5];
    float* out = (float*)d_out;
    int n = in_sizes[0] / 512;
    int nTiles = n / 32;
    int rem = n - nTiles * 32;
    cudaFuncSetAttribute(fctp_mma, cudaFuncAttributeMaxDynamicSharedMemorySize, SMEM_TOTAL);
    if (nTiles > 0) {
        int grid = (nTiles + TPC - 1) / TPC;
        fctp_mma<<<grid, NT, SMEM_TOTAL>>>(nf, pf, w000, w011, w101, w110, out, nTiles);
    }
    if (rem > 0)
        fctp_tail<<<1, 128>>>(nf, pf, w000, w011, w101, w110, out, nTiles * 32, n);
}